// round 3
// baseline (speedup 1.0000x reference)
#include <cuda_runtime.h>

// Two Euler steps of a Gaussian-RBF point flow.
// Structure:
//   pass1  : dp1 partials over all 16384 rows, j split S1=2 ways across CTAs
//   mid    : combine partials -> shape1; build packed pass-2 source tables
//   pass2  : dp2 partials over 8192 target rows, j split S2=4 ways
//   final  : combine partials -> output
// Each lane owns 2 rows; inner math uses packed fma.rn.f32x2 (FFMA2).
// Per-j operands staged in smem PRE-DUPLICATED ((u,u),(v,v),(a,a),(px,px),(py,py))
// so packed operands are direct LDS.128 broadcasts.

#define NSRC  2048
#define NTGT  2048
#define NLAND 4096
#define NB    4
#define TAUF  0.5f
#define LOG2E 1.4426950408889634f

typedef unsigned long long ull;

// Cross-kernel scratch (device globals; no allocation).
__device__ float2 g_p1[2][NB * NLAND];    // pass1 partial dp
__device__ float2 g_p2[4][NB * NTGT];     // pass2 partial dp
__device__ float4 g_pk_uv[NB * NSRC];     // (u,u,v,v)  from shape1 source pts
__device__ float4 g_pk_ap[NB * NSRC];     // (a,a,px,px)
__device__ float2 g_pk_py[NB * NSRC];     // (py,py)
__device__ float2 g_s1t[NB * NTGT];       // shape1 of target rows

__device__ __forceinline__ float ex2f(float x) {
    float y;
    asm("ex2.approx.ftz.f32 %0, %1;" : "=f"(y) : "f"(x));
    return y;
}
__device__ __forceinline__ ull fma2(ull a, ull b, ull c) {
    ull d;
    asm("fma.rn.f32x2 %0, %1, %2, %3;" : "=l"(d) : "l"(a), "l"(b), "l"(c));
    return d;
}
__device__ __forceinline__ ull add2(ull a, ull b) {
    ull d;
    asm("add.rn.f32x2 %0, %1, %2;" : "=l"(d) : "l"(a), "l"(b));
    return d;
}
__device__ __forceinline__ ull pack2(float lo, float hi) {
    ull d;
    asm("mov.b64 %0, {%1, %2};" : "=l"(d) : "f"(lo), "f"(hi));
    return d;
}
__device__ __forceinline__ void unpack2(ull v, float& lo, float& hi) {
    asm("mov.b64 {%0, %1}, %2;" : "=f"(lo), "=f"(hi) : "l"(v));
}

// Packed inner step for one j: arg = (u,v)·(x,y) + a + cri ; acc += 2^arg * p
__device__ __forceinline__ void rbf_step(
    const float4* __restrict__ sUV, const float4* __restrict__ sAP,
    const float2* __restrict__ sPY, int j,
    ull xp, ull yp, ull crip, ull& ax, ull& ay)
{
    ulonglong2 UV = *(const ulonglong2*)&sUV[j];   // .x=(u,u) .y=(v,v)
    ulonglong2 AP = *(const ulonglong2*)&sAP[j];   // .x=(a,a) .y=(px,px)
    ull PY = *(const ull*)&sPY[j];                 // (py,py)
    ull arg = add2(fma2(UV.y, yp, fma2(UV.x, xp, AP.x)), crip);
    float a0, a1;
    unpack2(arg, a0, a1);
    ull wp = pack2(ex2f(a0), ex2f(a1));
    ax = fma2(wp, AP.y, ax);
    ay = fma2(wp, PY, ay);
}

// ---------------------------------------------------------------------------
// Pass 1: grid = 256 row-groups (64 rows) x 2 j-splits = 512 CTAs, 256 thr.
// Each warp handles 128 j; each lane 2 rows (r0, r0+32).
// ---------------------------------------------------------------------------
__global__ __launch_bounds__(256, 4) void pass1_kernel(
    const float2* __restrict__ mom,
    const float2* __restrict__ src,
    const float2* __restrict__ tgt,
    const float*  __restrict__ sig)
{
    __shared__ float4 sUV[1024];
    __shared__ float4 sAP[1024];
    __shared__ float2 sPY[1024];
    __shared__ ull sRX[8][32];
    __shared__ ull sRY[8][32];

    const int g    = blockIdx.x;
    const int grp  = g >> 1;          // row group (0..255)
    const int s    = g & 1;           // j split
    const int i0   = grp * 64;        // global row base (0..16383)
    const int b    = i0 >> 12;
    const int li   = i0 & (NLAND - 1);
    const int tid  = threadIdx.x;
    const int w    = tid >> 5;
    const int lane = tid & 31;

    const float c2 = -LOG2E / sig[0];
    const float m2 = -2.0f * c2;

    const int jgb = b * NSRC + s * 1024;
    for (int jj = tid; jj < 1024; jj += 256) {
        float2 sp = src[jgb + jj];
        float2 p  = mom[jgb + jj];
        float u = m2 * sp.x, v = m2 * sp.y;
        float a = c2 * (sp.x * sp.x + sp.y * sp.y);
        sUV[jj] = make_float4(u, u, v, v);
        sAP[jj] = make_float4(a, a, p.x, p.x);
        sPY[jj] = make_float2(p.y, p.y);
    }
    __syncthreads();

    const int r0 = li + lane, r1 = r0 + 32;       // both on same side of 2048
    float2 X0 = (li < NSRC) ? src[b * NSRC + r0] : tgt[b * NTGT + r0 - NSRC];
    float2 X1 = (li < NSRC) ? src[b * NSRC + r1] : tgt[b * NTGT + r1 - NSRC];
    const ull xp = pack2(X0.x, X1.x);
    const ull yp = pack2(X0.y, X1.y);
    const ull crip = pack2(c2 * (X0.x * X0.x + X0.y * X0.y),
                           c2 * (X1.x * X1.x + X1.y * X1.y));

    ull ax0 = 0ull, ay0 = 0ull, ax1 = 0ull, ay1 = 0ull;  // packed (0.f,0.f)
    const int jb = w * 128;
    #pragma unroll
    for (int t = 0; t < 128; t += 2) {
        rbf_step(sUV, sAP, sPY, jb + t,     xp, yp, crip, ax0, ay0);
        rbf_step(sUV, sAP, sPY, jb + t + 1, xp, yp, crip, ax1, ay1);
    }
    sRX[w][lane] = add2(ax0, ax1);
    sRY[w][lane] = add2(ay0, ay1);
    __syncthreads();

    if (w == 0) {
        ull sx = sRX[0][lane], sy = sRY[0][lane];
        #pragma unroll
        for (int ww = 1; ww < 8; ww++) {
            sx = add2(sx, sRX[ww][lane]);
            sy = add2(sy, sRY[ww][lane]);
        }
        float x0, x1, y0, y1;
        unpack2(sx, x0, x1);
        unpack2(sy, y0, y1);
        g_p1[s][i0 + lane]      = make_float2(x0, y0);
        g_p1[s][i0 + lane + 32] = make_float2(x1, y1);
    }
}

// ---------------------------------------------------------------------------
// Mid: combine pass1 partials -> shape1; build pass-2 packed tables.
//   grid 64 x 256 (16384 rows)
// ---------------------------------------------------------------------------
__global__ __launch_bounds__(256) void mid_kernel(
    const float2* __restrict__ mom,
    const float2* __restrict__ src,
    const float2* __restrict__ tgt,
    const float*  __restrict__ sig)
{
    const int i = blockIdx.x * 256 + threadIdx.x;   // 0..16383
    const float c2 = -LOG2E / sig[0];
    const float m2 = -2.0f * c2;

    float2 d0 = g_p1[0][i], d1 = g_p1[1][i];
    const int b = i >> 12, r = i & (NLAND - 1);
    float2 X = (r < NSRC) ? src[b * NSRC + r] : tgt[b * NTGT + r - NSRC];
    float s1x = fmaf(TAUF, d0.x + d1.x, X.x);
    float s1y = fmaf(TAUF, d0.y + d1.y, X.y);

    if (r < NSRC) {
        float2 p = mom[b * NSRC + r];
        const int j = b * NSRC + r;
        float u = m2 * s1x, v = m2 * s1y;
        float a = c2 * (s1x * s1x + s1y * s1y);
        g_pk_uv[j] = make_float4(u, u, v, v);
        g_pk_ap[j] = make_float4(a, a, p.x, p.x);
        g_pk_py[j] = make_float2(p.y, p.y);
    } else {
        g_s1t[b * NTGT + r - NSRC] = make_float2(s1x, s1y);
    }
}

// ---------------------------------------------------------------------------
// Pass 2: grid = 128 row-groups (64 rows) x 4 j-splits = 512 CTAs, 256 thr.
// Each warp handles 64 j.
// ---------------------------------------------------------------------------
__global__ __launch_bounds__(256, 4) void pass2_kernel(
    const float*  __restrict__ sig)
{
    __shared__ float4 sUV[512];
    __shared__ float4 sAP[512];
    __shared__ float2 sPY[512];
    __shared__ ull sRX[8][32];
    __shared__ ull sRY[8][32];

    const int g    = blockIdx.x;
    const int grp  = g >> 2;          // row group (0..127)
    const int s    = g & 3;           // j split
    const int i0   = grp * 64;        // global target row base (0..8191)
    const int b    = i0 >> 11;
    const int tid  = threadIdx.x;
    const int w    = tid >> 5;
    const int lane = tid & 31;

    const float c2 = -LOG2E / sig[0];

    const int jgb = b * NSRC + s * 512;
    for (int jj = tid; jj < 512; jj += 256) {
        sUV[jj] = g_pk_uv[jgb + jj];
        sAP[jj] = g_pk_ap[jgb + jj];
        sPY[jj] = g_pk_py[jgb + jj];
    }
    __syncthreads();

    float2 X0 = g_s1t[i0 + lane];
    float2 X1 = g_s1t[i0 + lane + 32];
    const ull xp = pack2(X0.x, X1.x);
    const ull yp = pack2(X0.y, X1.y);
    const ull crip = pack2(c2 * (X0.x * X0.x + X0.y * X0.y),
                           c2 * (X1.x * X1.x + X1.y * X1.y));

    ull ax0 = 0ull, ay0 = 0ull, ax1 = 0ull, ay1 = 0ull;
    const int jb = w * 64;
    #pragma unroll
    for (int t = 0; t < 64; t += 2) {
        rbf_step(sUV, sAP, sPY, jb + t,     xp, yp, crip, ax0, ay0);
        rbf_step(sUV, sAP, sPY, jb + t + 1, xp, yp, crip, ax1, ay1);
    }
    sRX[w][lane] = add2(ax0, ax1);
    sRY[w][lane] = add2(ay0, ay1);
    __syncthreads();

    if (w == 0) {
        ull sx = sRX[0][lane], sy = sRY[0][lane];
        #pragma unroll
        for (int ww = 1; ww < 8; ww++) {
            sx = add2(sx, sRX[ww][lane]);
            sy = add2(sy, sRY[ww][lane]);
        }
        float x0, x1, y0, y1;
        unpack2(sx, x0, x1);
        unpack2(sy, y0, y1);
        g_p2[s][i0 + lane]      = make_float2(x0, y0);
        g_p2[s][i0 + lane + 32] = make_float2(x1, y1);
    }
}

// ---------------------------------------------------------------------------
// Final: combine pass2 partials -> output.  grid 32 x 256 (8192 rows)
// ---------------------------------------------------------------------------
__global__ __launch_bounds__(256) void final_kernel(float2* __restrict__ out)
{
    const int i = blockIdx.x * 256 + threadIdx.x;   // 0..8191
    float2 d0 = g_p2[0][i], d1 = g_p2[1][i];
    float2 d2 = g_p2[2][i], d3 = g_p2[3][i];
    float2 X = g_s1t[i];
    out[i] = make_float2(fmaf(TAUF, (d0.x + d1.x) + (d2.x + d3.x), X.x),
                         fmaf(TAUF, (d0.y + d1.y) + (d2.y + d3.y), X.y));
}

// ---------------------------------------------------------------------------
extern "C" void kernel_launch(void* const* d_in, const int* in_sizes, int n_in,
                              void* d_out, int out_size)
{
    const float2* mom = (const float2*)d_in[0];
    const float2* src = (const float2*)d_in[1];
    const float2* tgt = (const float2*)d_in[2];
    const float*  sig = (const float*)d_in[3];
    float2* out = (float2*)d_out;

    pass1_kernel<<<512, 256>>>(mom, src, tgt, sig);
    mid_kernel<<<64, 256>>>(mom, src, tgt, sig);
    pass2_kernel<<<512, 256>>>(sig);
    final_kernel<<<32, 256>>>(out);
}

// round 4
// speedup vs baseline: 1.1230x; 1.1230x over previous
#include <cuda_runtime.h>

// Two Euler steps of a Gaussian-RBF point flow — 2-launch structure.
//   pass1: dp1 for all 16384 rows (full j-range per CTA, 8-warp j-split
//          inside the CTA); writes pass-2 pair-packed source tables + shape1.
//   pass2: dp2 for 8192 target rows (full j-range per CTA, 16-warp j-split);
//          writes the output directly.
// FFMA2 packing is over PAIRS OF SOURCE POINTS (j, j+1): each lane owns one
// output row; per packed step it evaluates two Gaussians with
// fma.rn.f32x2 + 2x ex2.approx. Tables are staged in smem pre-paired
// ((u0,u1),(v0,v1),(a0,a1),(px0,px1),(py0,py1)) -> LDS.128 broadcasts.

#define NSRC  2048
#define NTGT  2048
#define NLAND 4096
#define NB    4
#define NPAIR 1024
#define TAUF  0.5f
#define LOG2E 1.4426950408889634f

typedef unsigned long long ull;

// Cross-kernel scratch (device globals; no allocation).
__device__ float4 g_pk_uv[NB * NPAIR];   // (u0,u1,v0,v1)   from shape1 source pts
__device__ float4 g_pk_ap[NB * NPAIR];   // (a0,a1,px0,px1)
__device__ float2 g_pk_py[NB * NPAIR];   // (py0,py1)
__device__ float2 g_s1t[NB * NTGT];      // shape1 of target rows

__device__ __forceinline__ float ex2f(float x) {
    float y;
    asm("ex2.approx.ftz.f32 %0, %1;" : "=f"(y) : "f"(x));
    return y;
}
__device__ __forceinline__ ull fma2(ull a, ull b, ull c) {
    ull d;
    asm("fma.rn.f32x2 %0, %1, %2, %3;" : "=l"(d) : "l"(a), "l"(b), "l"(c));
    return d;
}
__device__ __forceinline__ ull add2(ull a, ull b) {
    ull d;
    asm("add.rn.f32x2 %0, %1, %2;" : "=l"(d) : "l"(a), "l"(b));
    return d;
}
__device__ __forceinline__ ull pack2(float lo, float hi) {
    ull d;
    asm("mov.b64 %0, {%1, %2};" : "=l"(d) : "f"(lo), "f"(hi));
    return d;
}
__device__ __forceinline__ void unpack2(ull v, float& lo, float& hi) {
    asm("mov.b64 {%0, %1}, %2;" : "=f"(lo), "=f"(hi) : "l"(v));
}

// One packed step: evaluates Gaussians for source points (2q, 2q+1) against
// this lane's row; accumulates packed (even-j, odd-j) partial sums.
__device__ __forceinline__ void rbf_pair(
    const float4* __restrict__ sUV, const float4* __restrict__ sAP,
    const float2* __restrict__ sPY, int q,
    ull xp, ull yp, ull crip, ull& ax, ull& ay)
{
    ulonglong2 UV = *(const ulonglong2*)&sUV[q];   // .x=(u0,u1) .y=(v0,v1)
    ulonglong2 AP = *(const ulonglong2*)&sAP[q];   // .x=(a0,a1) .y=(px0,px1)
    ull PY = *(const ull*)&sPY[q];                 // (py0,py1)
    ull arg = add2(fma2(UV.y, yp, fma2(UV.x, xp, AP.x)), crip);
    float a0, a1;
    unpack2(arg, a0, a1);
    ull wp = pack2(ex2f(a0), ex2f(a1));
    ax = fma2(wp, AP.y, ax);
    ay = fma2(wp, PY, ay);
}

// ---------------------------------------------------------------------------
// Pass 1: 512 CTAs x 256 thr. CTA = 32 rows; warp w covers pairs
// [w*128, w*128+128) (256 j). Epilogue builds pass-2 tables / shape1.
// ---------------------------------------------------------------------------
__global__ __launch_bounds__(256, 4) void pass1_kernel(
    const float2* __restrict__ mom,
    const float2* __restrict__ src,
    const float2* __restrict__ tgt,
    const float*  __restrict__ sig)
{
    __shared__ float4 sUV[NPAIR];
    __shared__ float4 sAP[NPAIR];
    __shared__ float2 sPY[NPAIR];
    __shared__ ull sRX[8][32];
    __shared__ ull sRY[8][32];

    const int i0   = blockIdx.x * 32;       // global land row base (0..16383)
    const int b    = i0 >> 12;
    const int li   = i0 & (NLAND - 1);
    const int tid  = threadIdx.x;
    const int w    = tid >> 5;
    const int lane = tid & 31;

    const float c2 = -LOG2E / sig[0];
    const float m2 = -2.0f * c2;

    const float2* __restrict__ srcb = src + b * NSRC;
    const float2* __restrict__ momb = mom + b * NSRC;

    for (int q = tid; q < NPAIR; q += 256) {
        float2 s0 = srcb[2 * q],     s1 = srcb[2 * q + 1];
        float2 p0 = momb[2 * q],     p1 = momb[2 * q + 1];
        sUV[q] = make_float4(m2 * s0.x, m2 * s1.x, m2 * s0.y, m2 * s1.y);
        sAP[q] = make_float4(c2 * (s0.x * s0.x + s0.y * s0.y),
                             c2 * (s1.x * s1.x + s1.y * s1.y), p0.x, p1.x);
        sPY[q] = make_float2(p0.y, p1.y);
    }
    __syncthreads();

    const int i = li + lane;                // row within batch (same side for CTA)
    float2 X = (li < NSRC) ? srcb[i] : tgt[b * NTGT + i - NSRC];
    const ull xp = pack2(X.x, X.x);
    const ull yp = pack2(X.y, X.y);
    const float cri = c2 * (X.x * X.x + X.y * X.y);
    const ull crip = pack2(cri, cri);

    ull ax0 = 0ull, ay0 = 0ull, ax1 = 0ull, ay1 = 0ull;
    const int qb = w * 128;
    #pragma unroll 8
    for (int t = 0; t < 128; t += 2) {
        rbf_pair(sUV, sAP, sPY, qb + t,     xp, yp, crip, ax0, ay0);
        rbf_pair(sUV, sAP, sPY, qb + t + 1, xp, yp, crip, ax1, ay1);
    }
    sRX[w][lane] = add2(ax0, ax1);
    sRY[w][lane] = add2(ay0, ay1);
    __syncthreads();

    if (w == 0) {
        ull sx = sRX[0][lane], sy = sRY[0][lane];
        #pragma unroll
        for (int ww = 1; ww < 8; ww++) {
            sx = add2(sx, sRX[ww][lane]);
            sy = add2(sy, sRY[ww][lane]);
        }
        float e0, e1, f0, f1;
        unpack2(sx, e0, e1);
        unpack2(sy, f0, f1);
        float s1x = fmaf(TAUF, e0 + e1, X.x);
        float s1y = fmaf(TAUF, f0 + f1, X.y);

        if (li < NSRC) {
            // Build pass-2 pair-packed tables from shape1 source positions.
            float2 p = momb[i];
            float u = m2 * s1x, v = m2 * s1y;
            float a = c2 * (s1x * s1x + s1y * s1y);
            float uh  = __shfl_xor_sync(0xffffffffu, u,   1);
            float vh  = __shfl_xor_sync(0xffffffffu, v,   1);
            float ah  = __shfl_xor_sync(0xffffffffu, a,   1);
            float pxh = __shfl_xor_sync(0xffffffffu, p.x, 1);
            float pyh = __shfl_xor_sync(0xffffffffu, p.y, 1);
            if ((lane & 1) == 0) {
                const int q = (b * NSRC + i) >> 1;   // global pair index
                g_pk_uv[q] = make_float4(u, uh, v, vh);
                g_pk_ap[q] = make_float4(a, ah, p.x, pxh);
                g_pk_py[q] = make_float2(p.y, pyh);
            }
        } else {
            g_s1t[b * NTGT + i - NSRC] = make_float2(s1x, s1y);
        }
    }
}

// ---------------------------------------------------------------------------
// Pass 2: 256 CTAs x 512 thr (16 warps). CTA = 32 target rows; warp w covers
// pairs [w*64, w*64+64) (128 j). Writes output directly.
// ---------------------------------------------------------------------------
__global__ __launch_bounds__(512, 2) void pass2_kernel(
    const float*  __restrict__ sig,
    float2*       __restrict__ out)
{
    __shared__ float4 sUV[NPAIR];
    __shared__ float4 sAP[NPAIR];
    __shared__ float2 sPY[NPAIR];
    __shared__ ull sRX[8][32];
    __shared__ ull sRY[8][32];

    const int i0   = blockIdx.x * 32;       // global target row base (0..8191)
    const int b    = i0 >> 11;
    const int tid  = threadIdx.x;
    const int w    = tid >> 5;
    const int lane = tid & 31;

    const float c2 = -LOG2E / sig[0];

    const int qg = b * NPAIR;
    for (int q = tid; q < NPAIR; q += 512) {
        sUV[q] = g_pk_uv[qg + q];
        sAP[q] = g_pk_ap[qg + q];
        sPY[q] = g_pk_py[qg + q];
    }
    __syncthreads();

    const int i = i0 + lane;
    float2 X = g_s1t[i];
    const ull xp = pack2(X.x, X.x);
    const ull yp = pack2(X.y, X.y);
    const float cri = c2 * (X.x * X.x + X.y * X.y);
    const ull crip = pack2(cri, cri);

    ull ax0 = 0ull, ay0 = 0ull, ax1 = 0ull, ay1 = 0ull;
    const int qb = w * 64;
    #pragma unroll 8
    for (int t = 0; t < 64; t += 2) {
        rbf_pair(sUV, sAP, sPY, qb + t,     xp, yp, crip, ax0, ay0);
        rbf_pair(sUV, sAP, sPY, qb + t + 1, xp, yp, crip, ax1, ay1);
    }
    ull ax = add2(ax0, ax1);
    ull ay = add2(ay0, ay1);

    // Two-stage reduction across 16 warps using an [8][32] buffer.
    if (w >= 8) {
        sRX[w - 8][lane] = ax;
        sRY[w - 8][lane] = ay;
    }
    __syncthreads();
    if (w < 8) {
        ax = add2(ax, sRX[w][lane]);        // own slot: read-modify-write safe
        ay = add2(ay, sRY[w][lane]);
        sRX[w][lane] = ax;
        sRY[w][lane] = ay;
    }
    __syncthreads();

    if (w == 0) {
        ull sx = sRX[0][lane], sy = sRY[0][lane];
        #pragma unroll
        for (int ww = 1; ww < 8; ww++) {
            sx = add2(sx, sRX[ww][lane]);
            sy = add2(sy, sRY[ww][lane]);
        }
        float e0, e1, f0, f1;
        unpack2(sx, e0, e1);
        unpack2(sy, f0, f1);
        out[i] = make_float2(fmaf(TAUF, e0 + e1, X.x),
                             fmaf(TAUF, f0 + f1, X.y));
    }
}

// ---------------------------------------------------------------------------
extern "C" void kernel_launch(void* const* d_in, const int* in_sizes, int n_in,
                              void* d_out, int out_size)
{
    const float2* mom = (const float2*)d_in[0];
    const float2* src = (const float2*)d_in[1];
    const float2* tgt = (const float2*)d_in[2];
    const float*  sig = (const float*)d_in[3];
    float2* out = (float2*)d_out;

    pass1_kernel<<<NB * NLAND / 32, 256>>>(mom, src, tgt, sig);
    pass2_kernel<<<NB * NTGT / 32, 512>>>(sig, out);
}

// round 6
// speedup vs baseline: 1.1243x; 1.0012x over previous
#include <cuda_runtime.h>

// Two Euler steps of a Gaussian-RBF point flow — 2-launch structure.
// Inner exponent is the SAFE combined form arg = u*x + v*y + a + cri
// (== -|c| * |x_i - s_j|^2  <= 0, so 2^arg in [0,1] always; the round-5
// factored form overflowed for displaced shape1 rows).
// FFMA2 packs pairs of source points (j0,j1); lane = output row.
// Tables staged in smem pre-paired -> LDS.128 broadcasts.

#define NSRC  2048
#define NTGT  2048
#define NLAND 4096
#define NB    4
#define NPAIR 1024
#define TAUF  0.5f
#define LOG2E 1.4426950408889634f

typedef unsigned long long ull;

// Cross-kernel scratch (device globals; no allocation).
__device__ float4 g_pk_uv[NB * NPAIR];   // (u0,u1,v0,v1)   from shape1 source pts
__device__ float4 g_pk_ap[NB * NPAIR];   // (a0,a1,px0,px1)
__device__ float2 g_pk_py[NB * NPAIR];   // (py0,py1)
__device__ float2 g_s1t[NB * NTGT];      // shape1 of target rows

__device__ __forceinline__ float ex2f(float x) {
    float y;
    asm("ex2.approx.ftz.f32 %0, %1;" : "=f"(y) : "f"(x));
    return y;
}
__device__ __forceinline__ ull fma2(ull a, ull b, ull c) {
    ull d;
    asm("fma.rn.f32x2 %0, %1, %2, %3;" : "=l"(d) : "l"(a), "l"(b), "l"(c));
    return d;
}
__device__ __forceinline__ ull add2(ull a, ull b) {
    ull d;
    asm("add.rn.f32x2 %0, %1, %2;" : "=l"(d) : "l"(a), "l"(b));
    return d;
}
__device__ __forceinline__ ull pack2(float lo, float hi) {
    ull d;
    asm("mov.b64 %0, {%1, %2};" : "=l"(d) : "f"(lo), "f"(hi));
    return d;
}
__device__ __forceinline__ void unpack2(ull v, float& lo, float& hi) {
    asm("mov.b64 {%0, %1}, %2;" : "=f"(lo), "=f"(hi) : "l"(v));
}

// One packed step: Gaussians for source points (2q, 2q+1) vs this lane's row.
// crip = (cri,cri) packed; arg = uv·xy + a + cri  <= 0 (overflow-safe).
__device__ __forceinline__ void rbf_pair(
    const float4* __restrict__ sUV, const float4* __restrict__ sAP,
    const float2* __restrict__ sPY, int q,
    ull xp, ull yp, ull crip, ull& ax, ull& ay)
{
    ulonglong2 UV = *(const ulonglong2*)&sUV[q];   // .x=(u0,u1) .y=(v0,v1)
    ulonglong2 AP = *(const ulonglong2*)&sAP[q];   // .x=(a0,a1) .y=(px0,px1)
    ull PY = *(const ull*)&sPY[q];                 // (py0,py1)
    ull arg = add2(fma2(UV.y, yp, fma2(UV.x, xp, AP.x)), crip);
    float a0, a1;
    unpack2(arg, a0, a1);
    ull wp = pack2(ex2f(a0), ex2f(a1));
    ax = fma2(wp, AP.y, ax);
    ay = fma2(wp, PY, ay);
}

// ---------------------------------------------------------------------------
// Pass 1: 512 CTAs x 256 thr. CTA = 32 rows; warp w covers q in
// [w*128, w*128+128). Epilogue builds pass-2 tables / shape1.
// ---------------------------------------------------------------------------
__global__ __launch_bounds__(256, 4) void pass1_kernel(
    const float2* __restrict__ mom,
    const float2* __restrict__ src,
    const float2* __restrict__ tgt,
    const float*  __restrict__ sig)
{
    __shared__ float4 sUV[NPAIR];
    __shared__ float4 sAP[NPAIR];
    __shared__ float2 sPY[NPAIR];
    __shared__ ull sRX[8][32];
    __shared__ ull sRY[8][32];

    const int i0   = blockIdx.x * 32;       // global land row base (0..16383)
    const int b    = i0 >> 12;
    const int li   = i0 & (NLAND - 1);
    const int tid  = threadIdx.x;
    const int w    = tid >> 5;
    const int lane = tid & 31;

    const float c2 = -LOG2E / sig[0];
    const float m2 = -2.0f * c2;

    const float2* __restrict__ srcb = src + b * NSRC;
    const float2* __restrict__ momb = mom + b * NSRC;

    for (int q = tid; q < NPAIR; q += 256) {
        float2 s0 = srcb[2 * q],     s1 = srcb[2 * q + 1];
        float2 p0 = momb[2 * q],     p1 = momb[2 * q + 1];
        sUV[q] = make_float4(m2 * s0.x, m2 * s1.x, m2 * s0.y, m2 * s1.y);
        sAP[q] = make_float4(c2 * (s0.x * s0.x + s0.y * s0.y),
                             c2 * (s1.x * s1.x + s1.y * s1.y), p0.x, p1.x);
        sPY[q] = make_float2(p0.y, p1.y);
    }
    __syncthreads();

    const int i = li + lane;                // row within batch (same side for CTA)
    float2 X = (li < NSRC) ? srcb[i] : tgt[b * NTGT + i - NSRC];
    const ull xp = pack2(X.x, X.x);
    const ull yp = pack2(X.y, X.y);
    const float cri = c2 * (X.x * X.x + X.y * X.y);
    const ull crip = pack2(cri, cri);

    ull ax0 = 0ull, ay0 = 0ull, ax1 = 0ull, ay1 = 0ull;
    const int qb = w * 128;
    #pragma unroll 8
    for (int t = 0; t < 128; t += 2) {
        rbf_pair(sUV, sAP, sPY, qb + t,     xp, yp, crip, ax0, ay0);
        rbf_pair(sUV, sAP, sPY, qb + t + 1, xp, yp, crip, ax1, ay1);
    }
    sRX[w][lane] = add2(ax0, ax1);
    sRY[w][lane] = add2(ay0, ay1);
    __syncthreads();

    if (w == 0) {
        ull sx = sRX[0][lane], sy = sRY[0][lane];
        #pragma unroll
        for (int ww = 1; ww < 8; ww++) {
            sx = add2(sx, sRX[ww][lane]);
            sy = add2(sy, sRY[ww][lane]);
        }
        float e0, e1, f0, f1;
        unpack2(sx, e0, e1);
        unpack2(sy, f0, f1);
        float s1x = fmaf(TAUF, e0 + e1, X.x);
        float s1y = fmaf(TAUF, f0 + f1, X.y);

        if (li < NSRC) {
            // Build pass-2 pair-packed tables from shape1 source positions.
            float2 p = momb[i];
            float u = m2 * s1x, v = m2 * s1y;
            float a = c2 * (s1x * s1x + s1y * s1y);
            float uh  = __shfl_xor_sync(0xffffffffu, u,   1);
            float vh  = __shfl_xor_sync(0xffffffffu, v,   1);
            float ah  = __shfl_xor_sync(0xffffffffu, a,   1);
            float pxh = __shfl_xor_sync(0xffffffffu, p.x, 1);
            float pyh = __shfl_xor_sync(0xffffffffu, p.y, 1);
            if ((lane & 1) == 0) {
                const int q = (b * NSRC + i) >> 1;   // global pair index
                g_pk_uv[q] = make_float4(u, uh, v, vh);
                g_pk_ap[q] = make_float4(a, ah, p.x, pxh);
                g_pk_py[q] = make_float2(p.y, pyh);
            }
        } else {
            g_s1t[b * NTGT + i - NSRC] = make_float2(s1x, s1y);
        }
    }
}

// ---------------------------------------------------------------------------
// Pass 2: 256 CTAs x 256 thr (8 warps). CTA = 32 target rows; warp w covers
// q in [w*128, w*128+128). 4 independent accumulator streams for ILP.
// Writes output directly.
// ---------------------------------------------------------------------------
__global__ __launch_bounds__(256, 3) void pass2_kernel(
    const float*  __restrict__ sig,
    float2*       __restrict__ out)
{
    __shared__ float4 sUV[NPAIR];
    __shared__ float4 sAP[NPAIR];
    __shared__ float2 sPY[NPAIR];
    __shared__ ull sRX[8][32];
    __shared__ ull sRY[8][32];

    const int i0   = blockIdx.x * 32;       // global target row base (0..8191)
    const int b    = i0 >> 11;
    const int tid  = threadIdx.x;
    const int w    = tid >> 5;
    const int lane = tid & 31;

    const float c2 = -LOG2E / sig[0];

    const int qg = b * NPAIR;
    for (int q = tid; q < NPAIR; q += 256) {
        sUV[q] = g_pk_uv[qg + q];
        sAP[q] = g_pk_ap[qg + q];
        sPY[q] = g_pk_py[qg + q];
    }
    __syncthreads();

    const int i = i0 + lane;
    float2 X = g_s1t[i];
    const ull xp = pack2(X.x, X.x);
    const ull yp = pack2(X.y, X.y);
    const float cri = c2 * (X.x * X.x + X.y * X.y);
    const ull crip = pack2(cri, cri);

    ull ax0 = 0ull, ay0 = 0ull, ax1 = 0ull, ay1 = 0ull;
    ull ax2 = 0ull, ay2 = 0ull, ax3 = 0ull, ay3 = 0ull;
    const int qb = w * 128;
    #pragma unroll 4
    for (int t = 0; t < 128; t += 4) {
        rbf_pair(sUV, sAP, sPY, qb + t,     xp, yp, crip, ax0, ay0);
        rbf_pair(sUV, sAP, sPY, qb + t + 1, xp, yp, crip, ax1, ay1);
        rbf_pair(sUV, sAP, sPY, qb + t + 2, xp, yp, crip, ax2, ay2);
        rbf_pair(sUV, sAP, sPY, qb + t + 3, xp, yp, crip, ax3, ay3);
    }
    sRX[w][lane] = add2(add2(ax0, ax1), add2(ax2, ax3));
    sRY[w][lane] = add2(add2(ay0, ay1), add2(ay2, ay3));
    __syncthreads();

    if (w == 0) {
        ull sx = sRX[0][lane], sy = sRY[0][lane];
        #pragma unroll
        for (int ww = 1; ww < 8; ww++) {
            sx = add2(sx, sRX[ww][lane]);
            sy = add2(sy, sRY[ww][lane]);
        }
        float e0, e1, f0, f1;
        unpack2(sx, e0, e1);
        unpack2(sy, f0, f1);
        out[i] = make_float2(fmaf(TAUF, e0 + e1, X.x),
                             fmaf(TAUF, f0 + f1, X.y));
    }
}

// ---------------------------------------------------------------------------
extern "C" void kernel_launch(void* const* d_in, const int* in_sizes, int n_in,
                              void* d_out, int out_size)
{
    const float2* mom = (const float2*)d_in[0];
    const float2* src = (const float2*)d_in[1];
    const float2* tgt = (const float2*)d_in[2];
    const float*  sig = (const float*)d_in[3];
    float2* out = (float2*)d_out;

    pass1_kernel<<<NB * NLAND / 32, 256>>>(mom, src, tgt, sig);
    pass2_kernel<<<NB * NTGT / 32, 256>>>(sig, out);
}